// round 1
// baseline (speedup 1.0000x reference)
#include <cuda_runtime.h>

#define NPOS        22743
#define NB          64
#define CELLS_PER_B 7581            // 76*76 + 38*38 + 19*19
#define TOTAL_CELLS (NB * CELLS_PER_B)

// Accumulators: [0]=n_obj  [1]=s_xy  [2]=s_wh  [3]=s_cls  [4]=s_obj(weighted)
__device__ float g_acc[5];

// ANCHORS / stride, stride = 608/grid = {8,16,32} (exact in fp32)
__constant__ float c_anch[3][3][2] = {
    {{1.25f, 1.625f},  {2.0f,   3.75f},   {4.125f,    2.875f}},
    {{1.875f,2.8125f}, {3.875f, 2.8125f}, {3.6875f,   7.4375f}},
    {{3.625f,2.8125f}, {4.875f, 6.1875f}, {11.65625f, 10.1875f}},
};

__global__ void zero_acc_kernel() {
    if (threadIdx.x < 5) g_acc[threadIdx.x] = 0.0f;
}

// softplus(z) = log(1+e^z); for our z in [0,1] this is well-conditioned.
// bce(sigmoid(z), t) = softplus(z) - t*z
__device__ __forceinline__ float softplusf(float z) {
    return __logf(1.0f + __expf(z));
}

__global__ void __launch_bounds__(256)
yolo_loss_kernel(const float* __restrict__ x, const float* __restrict__ t) {
    int tid = blockIdx.x * 256 + threadIdx.x;

    float a_n = 0.f, a_xy = 0.f, a_wh = 0.f, a_cls = 0.f, a_obj = 0.f;

    if (tid < TOTAL_CELLS) {
        int b    = tid / CELLS_PER_B;
        int cell = tid - b * CELLS_PER_B;

        int sc, p0;
        float g, wobj;
        if (cell < 5776) {                    // 76x76
            sc = 0; p0 = cell * 3;                     g = 76.f; wobj = 1.f / 1108992.f;
        } else if (cell < 7220) {             // 38x38
            sc = 1; p0 = 17328 + (cell - 5776) * 3;    g = 38.f; wobj = 1.f / 277248.f;
        } else {                              // 19x19
            sc = 2; p0 = 21660 + (cell - 7220) * 3;    g = 19.f; wobj = 1.f / 69312.f;
        }

        int base = (b * NPOS + p0) * 85;

        float iou[3], t4v[3], x4v[3];
        #pragma unroll
        for (int j = 0; j < 3; j++) {
            int off = base + j * 85;
            float tw = __ldg(t + off + 2) * g;
            float th = __ldg(t + off + 3) * g;
            t4v[j]   = __ldg(t + off + 4);
            x4v[j]   = __ldg(x + off + 4);
            float aw = c_anch[sc][j][0], ah = c_anch[sc][j][1];
            float inter = fminf(tw, aw) * fminf(th, ah);
            float uni   = tw * th + aw * ah - inter;
            iou[j] = inter / (uni + 1e-12f);
        }

        // argmax with first-occurrence tie-break (matches jnp.argmax)
        int best = 0;
        if (iou[1] > iou[0])    best = 1;
        if (iou[2] > iou[best]) best = 2;

        #pragma unroll
        for (int j = 0; j < 3; j++) {
            float keep = ((iou[j] <= 0.7f) || (j == best)) ? 1.0f : 0.0f;

            // objectness: bce(sigmoid(x4*keep), t4*keep)
            float z  = x4v[j] * keep;
            float tt = t4v[j] * keep;
            a_obj += wobj * (softplusf(z) - tt * z);

            if (t4v[j] > 0.0f) {              // ~2% of positions
                int off = base + j * 85;
                a_n   += 1.0f;
                // cls: bce(sigmoid(x4), t4)
                a_cls += softplusf(x4v[j]) - t4v[j] * x4v[j];

                float x0 = __ldg(x + off + 0), x1 = __ldg(x + off + 1);
                float x2 = __ldg(x + off + 2), x3 = __ldg(x + off + 3);
                float t0 = __ldg(t + off + 0), t1 = __ldg(t + off + 1);
                float t2 = __ldg(t + off + 2), t3 = __ldg(t + off + 3);

                // xy: bce(sigmoid(x), t)
                a_xy += (softplusf(x0) - t0 * x0) + (softplusf(x1) - t1 * x1);

                // wh: bce(clip(x, eps, 1-eps), t)  [1-eps rounds to 1.0f in fp32]
                float p2 = fmaxf(x2, 1e-12f);
                float p3 = fmaxf(x3, 1e-12f);
                a_wh += -(t2 * __logf(p2) + (1.0f - t2) * __logf(1.0f - p2));
                a_wh += -(t3 * __logf(p3) + (1.0f - t3) * __logf(1.0f - p3));
            }
        }
    }

    // ---- reduction: warp shuffle -> shared -> global atomics ----
    #pragma unroll
    for (int o = 16; o > 0; o >>= 1) {
        a_n   += __shfl_down_sync(0xFFFFFFFFu, a_n,   o);
        a_xy  += __shfl_down_sync(0xFFFFFFFFu, a_xy,  o);
        a_wh  += __shfl_down_sync(0xFFFFFFFFu, a_wh,  o);
        a_cls += __shfl_down_sync(0xFFFFFFFFu, a_cls, o);
        a_obj += __shfl_down_sync(0xFFFFFFFFu, a_obj, o);
    }

    __shared__ float sh[5];
    if (threadIdx.x < 5) sh[threadIdx.x] = 0.0f;
    __syncthreads();
    if ((threadIdx.x & 31) == 0) {
        atomicAdd(&sh[0], a_n);
        atomicAdd(&sh[1], a_xy);
        atomicAdd(&sh[2], a_wh);
        atomicAdd(&sh[3], a_cls);
        atomicAdd(&sh[4], a_obj);
    }
    __syncthreads();
    if (threadIdx.x < 5) atomicAdd(&g_acc[threadIdx.x], sh[threadIdx.x]);
}

__global__ void finalize_kernel(float* __restrict__ out) {
    float n = fmaxf(g_acc[0], 1.0f);
    out[0] = (g_acc[1] + g_acc[2]) / (2.0f * n) + g_acc[3] / n + g_acc[4];
}

extern "C" void kernel_launch(void* const* d_in, const int* in_sizes, int n_in,
                              void* d_out, int out_size) {
    const float* x = (const float*)d_in[0];
    const float* t = (const float*)d_in[1];
    float* out = (float*)d_out;

    zero_acc_kernel<<<1, 32>>>();
    int nblk = (TOTAL_CELLS + 255) / 256;
    yolo_loss_kernel<<<nblk, 256>>>(x, t);
    finalize_kernel<<<1, 1>>>(out);
}

// round 2
// speedup vs baseline: 1.0931x; 1.0931x over previous
#include <cuda_runtime.h>

#define NPOS        22743
#define NB          64
#define CELLS_PER_B 7581            // 76*76 + 38*38 + 19*19
#define BLK         256
#define BX          30              // ceil(7581/256)
#define TOTAL_BLOCKS (BX * NB)

// Accumulators: [0]=n_obj  [1]=s_xy  [2]=s_wh  [3]=s_cls  [4]=s_obj(weighted)
__device__ float        g_acc[5];
__device__ unsigned int g_cnt;

// ANCHORS / stride, stride = 608/grid = {8,16,32} (exact in fp32)
__constant__ float c_anch[3][3][2] = {
    {{1.25f, 1.625f},  {2.0f,   3.75f},   {4.125f,    2.875f}},
    {{1.875f,2.8125f}, {3.875f, 2.8125f}, {3.6875f,   7.4375f}},
    {{3.625f,2.8125f}, {4.875f, 6.1875f}, {11.65625f, 10.1875f}},
};

// bce(sigmoid(z), t) = softplus(z) - t*z
__device__ __forceinline__ float softplusf(float z) {
    return __logf(1.0f + __expf(z));
}

__global__ void __launch_bounds__(BLK)
yolo_loss_kernel(const float* __restrict__ x, const float* __restrict__ t,
                 float* __restrict__ out) {
    const int cell = blockIdx.x * BLK + threadIdx.x;
    const int b    = blockIdx.y;

    float a_n = 0.f, a_xy = 0.f, a_wh = 0.f, a_cls = 0.f, a_obj = 0.f;

    if (cell < CELLS_PER_B) {
        int sc, p0;
        float g, wobj;
        if (cell < 5776) {                    // 76x76
            sc = 0; p0 = cell * 3;                     g = 76.f; wobj = 1.f / 1108992.f;
        } else if (cell < 7220) {             // 38x38
            sc = 1; p0 = 17328 + (cell - 5776) * 3;    g = 38.f; wobj = 1.f / 277248.f;
        } else {                              // 19x19
            sc = 2; p0 = 21660 + (cell - 7220) * 3;    g = 19.f; wobj = 1.f / 69312.f;
        }

        const size_t base = ((size_t)b * NPOS + p0) * 85;
        const float* __restrict__ tb = t + base;
        const float* __restrict__ xb = x + base;

        float inter[3], d[3], t2r[3], t3r[3], t4v[3], x4v[3];
        #pragma unroll
        for (int j = 0; j < 3; j++) {
            const float* tp = tb + j * 85;
            t2r[j] = __ldg(tp + 2);
            t3r[j] = __ldg(tp + 3);
            t4v[j] = __ldg(tp + 4);
            x4v[j] = __ldg(xb + j * 85 + 4);
            float tw = t2r[j] * g, th = t3r[j] * g;
            float aw = c_anch[sc][j][0], ah = c_anch[sc][j][1];
            float in_ = fminf(tw, aw) * fminf(th, ah);
            inter[j] = in_;
            d[j]     = tw * th + aw * ah - in_ + 1e-12f;   // union + eps, > 0
        }

        // argmax of inter[j]/d[j] via cross-mult (d > 0); first-occurrence tie-break
        int best = 0;
        float ib = inter[0], db = d[0];
        if (inter[1] * db > ib * d[1]) { best = 1; ib = inter[1]; db = d[1]; }
        if (inter[2] * db > ib * d[2]) { best = 2; }

        #pragma unroll
        for (int j = 0; j < 3; j++) {
            bool keep = (inter[j] <= 0.7f * d[j]) || (j == best);

            // s = bce(sigmoid(x4), t4) = softplus(x4) - t4*x4
            float s = softplusf(x4v[j]) - t4v[j] * x4v[j];

            // obj: keep ? s : bce(sigmoid(0), 0) = ln 2
            a_obj += wobj * (keep ? s : 0.69314718055994531f);

            if (t4v[j] > 0.0f) {              // ~2% of positions
                const float* tp = tb + j * 85;
                const float* xp = xb + j * 85;
                a_n   += 1.0f;
                a_cls += s;

                float x0 = __ldg(xp + 0), x1 = __ldg(xp + 1);
                float x2 = __ldg(xp + 2), x3 = __ldg(xp + 3);
                float t0 = __ldg(tp + 0), t1 = __ldg(tp + 1);

                // xy: bce(sigmoid(x), t)
                a_xy += (softplusf(x0) - t0 * x0) + (softplusf(x1) - t1 * x1);

                // wh: bce(clip(x, eps, 1-eps), t)  [1-eps rounds to 1.0f in fp32]
                float p2 = fmaxf(x2, 1e-12f);
                float p3 = fmaxf(x3, 1e-12f);
                a_wh += -(t2r[j] * __logf(p2) + (1.0f - t2r[j]) * __logf(1.0f - p2));
                a_wh += -(t3r[j] * __logf(p3) + (1.0f - t3r[j]) * __logf(1.0f - p3));
            }
        }
    }

    // ---- reduction: warp shuffle -> shared -> global atomics ----
    #pragma unroll
    for (int o = 16; o > 0; o >>= 1) {
        a_n   += __shfl_down_sync(0xFFFFFFFFu, a_n,   o);
        a_xy  += __shfl_down_sync(0xFFFFFFFFu, a_xy,  o);
        a_wh  += __shfl_down_sync(0xFFFFFFFFu, a_wh,  o);
        a_cls += __shfl_down_sync(0xFFFFFFFFu, a_cls, o);
        a_obj += __shfl_down_sync(0xFFFFFFFFu, a_obj, o);
    }

    __shared__ float sh[5];
    if (threadIdx.x < 5) sh[threadIdx.x] = 0.0f;
    __syncthreads();
    if ((threadIdx.x & 31) == 0) {
        atomicAdd(&sh[0], a_n);
        atomicAdd(&sh[1], a_xy);
        atomicAdd(&sh[2], a_wh);
        atomicAdd(&sh[3], a_cls);
        atomicAdd(&sh[4], a_obj);
    }
    __syncthreads();
    if (threadIdx.x < 5) atomicAdd(&g_acc[threadIdx.x], sh[threadIdx.x]);

    // ---- last block finalizes and resets state for the next graph replay ----
    if (threadIdx.x == 0) {
        __threadfence();
        unsigned int done = atomicAdd(&g_cnt, 1u);
        if (done == TOTAL_BLOCKS - 1) {
            // coherent reads of the accumulators (atomics resolve in L2)
            float vn   = atomicAdd(&g_acc[0], 0.f);
            float vxy  = atomicAdd(&g_acc[1], 0.f);
            float vwh  = atomicAdd(&g_acc[2], 0.f);
            float vcls = atomicAdd(&g_acc[3], 0.f);
            float vobj = atomicAdd(&g_acc[4], 0.f);
            float n = fmaxf(vn, 1.0f);
            out[0] = (vxy + vwh) / (2.0f * n) + vcls / n + vobj;
            // reset for next call
            atomicExch(&g_acc[0], 0.f);
            atomicExch(&g_acc[1], 0.f);
            atomicExch(&g_acc[2], 0.f);
            atomicExch(&g_acc[3], 0.f);
            atomicExch(&g_acc[4], 0.f);
            atomicExch(&g_cnt, 0u);
        }
    }
}

extern "C" void kernel_launch(void* const* d_in, const int* in_sizes, int n_in,
                              void* d_out, int out_size) {
    const float* x = (const float*)d_in[0];
    const float* t = (const float*)d_in[1];
    float* out = (float*)d_out;

    dim3 grid(BX, NB);
    yolo_loss_kernel<<<grid, BLK>>>(x, t, out);
}